// round 6
// baseline (speedup 1.0000x reference)
#include <cuda_runtime.h>

// Problem constants (fixed by setup_inputs: B=8,T=4096,D=1024,A=32,S=16,TTL=64)
#define NB_B 8
#define NB_T 4096
#define NB_D 1024
#define NB_A 32
#define SP   16
#define HH   256           // H = max(ttl*4, span*4)
#define WW   (HH - SP + 1) // 241
#define NPAIR (NB_B * NB_A)
#define CH   4             // column chunks (CTAs) per pair
#define CG   64            // float4 groups per chunk (256 floats)
#define NG   (NB_D / 4)    // 256 float4 groups per row

// scratch: per-(pair,row) 4 chunk partial row-norms^2 (1 MB) + 3 scalars/chunk
__device__ float g_rshift[NPAIR * HH * CH];
__device__ float g_dot[NPAIR * CH];
__device__ float g_nf2[NPAIR * CH];
__device__ float g_nr2[NPAIR * CH];
__device__ unsigned int g_cnt[NPAIR];   // zero-init; reset by finalizer each call

__constant__ signed char c_alias[64] = {
  -1,-1,-1,-1,-1,-1,-1,-1,-1,-1,-1,
  11,-1,11,-1,-1,11,
  -1,-1,-1,-1,
  21,21,21,
  -1,-1,-1,-1,-1,-1,-1,
  31,31,31,
  -1,-1,-1,-1,-1,-1,-1,
  41,41,41,41,
  -1,-1,-1,-1,-1,-1,
  51,51,51,
  -1,-1,-1,-1,-1,-1,-1,-1,-1,-1
};

__global__ void __launch_bounds__(256, 3) cm_fused(
    const float* __restrict__ hidden,
    const float* __restrict__ anchor,
    const int*   __restrict__ ids,
    const int*   __restrict__ aend,
    float*       __restrict__ out)
{
  const int blk   = blockIdx.x;
  const int p     = blk >> 2;          // pair
  const int chunk = blk & 3;           // column chunk
  const int b     = p / NB_A;
  const int tid   = threadIdx.x;
  const int lane  = tid & 31;
  const int wp    = tid >> 5;          // 8 warps; warp w owns rows [w*32, w*32+32)

  __shared__ float4 scs[8 * 64];       // 4 KB column-sum combine
  __shared__ float  sfin[3 * 8];
  __shared__ unsigned int s_old;
  // finalizer-phase shared
  __shared__ float sred[48];
  __shared__ int   ftok[HH];
  __shared__ int   sp_[SP];
  __shared__ signed char s_alias[64];
  __shared__ int   s_root, s_has, s_atok;
  __shared__ float s_invden;
  __shared__ unsigned long long s_spanmask, s_cmask;
  __shared__ float s_shift;

  const int ae    = aend[p];
  const int start = ae + 1;

  const float4* __restrict__ hb =
      reinterpret_cast<const float4*>(hidden)
      + ((size_t)b * NB_T + start) * NG + chunk * CG;
  const float4* __restrict__ af =
      reinterpret_cast<const float4*>(anchor) + (size_t)p * NG + chunk * CG;

  // lane owns groups lane and lane+32 of this chunk
  const float4 a0 = af[lane];
  const float4 a1 = af[lane + 32];
  float4 cs0 = make_float4(0.f,0.f,0.f,0.f);
  float4 cs1 = make_float4(0.f,0.f,0.f,0.f);

  const int row0 = wp * 32;
  float* __restrict__ rsh = g_rshift + ((size_t)p * HH) * CH + chunk;

#pragma unroll 1
  for (int it = 0; it < 8; it++) {
    const int r = row0 + it * 4;
    float4 x[4], y[4];
#pragma unroll
    for (int j = 0; j < 4; j++) {
      x[j] = hb[(size_t)(r + j) * NG + lane];
      y[j] = hb[(size_t)(r + j) * NG + lane + 32];
    }
    float v[4];
#pragma unroll
    for (int j = 0; j < 4; j++) {
      cs0.x += x[j].x; cs0.y += x[j].y; cs0.z += x[j].z; cs0.w += x[j].w;
      cs1.x += y[j].x; cs1.y += y[j].y; cs1.z += y[j].z; cs1.w += y[j].w;
      float dx = x[j].x - a0.x, dy = x[j].y - a0.y;
      float dz = x[j].z - a0.z, dw = x[j].w - a0.w;
      float ex = y[j].x - a1.x, ey = y[j].y - a1.y;
      float ez = y[j].z - a1.z, ew = y[j].w - a1.w;
      v[j] = dx*dx + dy*dy + dz*dz + dw*dw + ex*ex + ey*ey + ez*ez + ew*ew;
    }
#pragma unroll
    for (int j = 0; j < 4; j++) {
#pragma unroll
      for (int o = 16; o; o >>= 1) v[j] += __shfl_xor_sync(0xffffffffu, v[j], o);
    }
    if (lane < 4) rsh[(r + lane) * CH] = v[lane];
  }

  // combine warps' column sums -> chunk scalars: dot, nf2, nr2
  scs[wp * 64 + lane]      = cs0;
  scs[wp * 64 + lane + 32] = cs1;
  __syncthreads();

  if (tid < 64) {
    float4 t = scs[tid];
#pragma unroll
    for (int w = 1; w < 8; w++) {
      float4 u = scs[w * 64 + tid];
      t.x += u.x; t.y += u.y; t.z += u.z; t.w += u.w;
    }
    float4 a = af[tid];
    float dot = a.x*t.x + a.y*t.y + a.z*t.z + a.w*t.w;
    float nf2 = t.x*t.x + t.y*t.y + t.z*t.z + t.w*t.w;
    float nr2 = a.x*a.x + a.y*a.y + a.z*a.z + a.w*a.w;
#pragma unroll
    for (int o = 16; o; o >>= 1) {
      dot += __shfl_xor_sync(0xffffffffu, dot, o);
      nf2 += __shfl_xor_sync(0xffffffffu, nf2, o);
      nr2 += __shfl_xor_sync(0xffffffffu, nr2, o);
    }
    if (lane == 0) {
      sfin[wp * 3 + 0] = dot; sfin[wp * 3 + 1] = nf2; sfin[wp * 3 + 2] = nr2;
    }
  }
  __syncthreads();
  if (tid == 0) {
    g_dot[blk] = sfin[0] + sfin[3];
    g_nf2[blk] = sfin[1] + sfin[4];
    g_nr2[blk] = sfin[2] + sfin[5];
  }

  // ---- last-CTA-done handoff ----
  __threadfence();
  __syncthreads();
  if (tid == 0) s_old = atomicAdd(&g_cnt[p], 1);
  __syncthreads();
  if (s_old != CH - 1) return;

  // this CTA finalizes pair p
  __threadfence();                 // acquire: other chunks' partials now visible
  if (tid == 0) g_cnt[p] = 0;      // reset for next graph replay

  if (tid < 64) s_alias[tid] = c_alias[tid];
  ftok[tid] = ids[b * NB_T + start + tid];
  if (tid < SP) sp_[tid] = ids[b * NB_T + ae - (SP - 1) + tid];
  if (tid == 0) s_atok = ids[b * NB_T + ae];

  // per-row norm: thread tid owns row tid; 4 chunk partials as one float4
  float4 rp4 = reinterpret_cast<const float4*>(g_rshift)[p * HH + tid];
  float rn = sqrtf(rp4.x + rp4.y + rp4.z + rp4.w);
#pragma unroll
  for (int o = 16; o; o >>= 1) rn += __shfl_xor_sync(0xffffffffu, rn, o);
  if (lane == 0) sred[40 + wp] = rn;
  __syncthreads();

  if (tid == 0) {
    float sh = 0.f;
#pragma unroll
    for (int k = 0; k < 8; k++) sh += sred[40 + k];
    s_shift = sh * (1.f / HH);

    // root / span analysis
    int root = -1;
    for (int s = 0; s < SP; s++) {
      int al = s_alias[sp_[s]];
      if (al >= 0) { root = al; break; }
    }
    if (root < 0) {
      int counts[SP]; int maxc = 0;
      for (int s = 0; s < SP; s++) {
        int c2 = 0;
        for (int s2 = 0; s2 < SP; s2++) c2 += (sp_[s2] == sp_[s]);
        counts[s] = c2; if (c2 > maxc) maxc = c2;
      }
      int mode = 64;
      for (int s = 0; s < SP; s++)
        if (counts[s] == maxc && sp_[s] < mode) mode = sp_[s];
      root = mode;
    }
    unsigned long long smask = 0ull; int den = 0;
    for (int s = 0; s < SP; s++) {
      bool first = true;
      for (int s2 = 0; s2 < s; s2++)
        if (sp_[s2] == sp_[s]) { first = false; break; }
      if (first) { den++; smask |= (1ull << sp_[s]); }
    }
    s_root = root;
    s_spanmask = smask;
    s_invden = 1.f / (float)den;
    s_has = (root == 11 || root == 21 || root == 31 || root == 41 || root == 51) ? 1 : 0;
    unsigned long long cm = 0ull;
    switch (root) {
      case 11: cm = (1ull<<11)|(1ull<<13)|(1ull<<16); break;
      case 21: cm = (1ull<<14)|(1ull<<15)|(1ull<<21)|(1ull<<22)|(1ull<<23); break;
      case 31: cm = (1ull<<15)|(1ull<<31)|(1ull<<32)|(1ull<<33); break;
      case 41: cm = (1ull<<41)|(1ull<<42)|(1ull<<43)|(1ull<<44); break;
      case 51: cm = (1ull<<15)|(1ull<<51)|(1ull<<52)|(1ull<<53); break;
      default: break;
    }
    s_cmask = cm;
  }
  __syncthreads();

  // per-window metrics (thread w handles window w, w < 241)
  int myeq = (ftok[tid] == s_atok) ? 1 : 0;

  float sims = -1e30f, rootp = 0.f, regime = 0.f, ssum = 0.f;
  int c06 = 0;
  if (tid < WW) {
    const int root = s_root;
    const unsigned long long cmask = s_cmask;
    float exact = 0.f, positional = 0.f;
    unsigned long long wmask = 0ull;
    int c_rp = 0, c_al = 0, c_hd = 0;
#pragma unroll
    for (int s = 0; s < SP; s++) {
      int t = ftok[tid + s];
      wmask |= (1ull << t);
      if (t == sp_[s]) { exact += 1.f; positional += (1.0f - 0.04f * (float)s); }
      c_rp += (t == root);
      c_al += ((int)s_alias[t] == root);
      c_hd += (int)((cmask >> t) & 1ull);
    }
    exact *= (1.f / 16.f);
    positional *= (1.f / 11.2f);
    float overlap = (float)__popcll(wmask & s_spanmask) * s_invden;
    rootp = (float)c_rp * (1.f / 16.f);
    float aliasc = (float)c_al * (1.f / 16.f);
    float hard   = (float)c_hd * (1.f / 16.f);
    regime = s_has ? (0.55f * hard  + 0.2f * overlap + 0.15f * aliasc + 0.1f  * rootp)
                   : (0.45f * exact + 0.3f * overlap + 0.1f  * aliasc + 0.15f * rootp);
    float sv = 0.25f * exact + 0.15f * overlap + 0.35f * positional + 0.25f * regime;
    sims = sv; ssum = sv;
    c06 = (sv >= 0.6f) ? 1 : 0;
  }

  float msims = sims, srp = rootp, srg = regime, sss = ssum;
  int ceq = myeq, c6 = c06;
#pragma unroll
  for (int o = 16; o; o >>= 1) {
    msims = fmaxf(msims, __shfl_xor_sync(0xffffffffu, msims, o));
    srp += __shfl_xor_sync(0xffffffffu, srp, o);
    srg += __shfl_xor_sync(0xffffffffu, srg, o);
    sss += __shfl_xor_sync(0xffffffffu, sss, o);
    ceq += __shfl_xor_sync(0xffffffffu, ceq, o);
    c6  += __shfl_xor_sync(0xffffffffu, c6, o);
  }
  if (lane == 0) {
    sred[wp]      = msims;
    sred[8 + wp]  = srp;
    sred[16 + wp] = srg;
    sred[24 + wp] = sss;
    sred[32 + wp] = (float)ceq;
    sred[40 + wp] = (float)c6;
  }
  __syncthreads();

  if (tid == 0) {
    float best = -1e30f, trp = 0.f, trg = 0.f, tss = 0.f, teq = 0.f, t6 = 0.f;
    for (int k = 0; k < 8; k++) {
      best = fmaxf(best, sred[k]);
      trp += sred[8 + k]; trg += sred[16 + k]; tss += sred[24 + k];
      teq += sred[32 + k]; t6 += sred[40 + k];
    }
    float dot = 0.f, nf2 = 0.f, nr2 = 0.f;
#pragma unroll
    for (int c = 0; c < CH; c++) {
      dot += g_dot[p * CH + c];
      nf2 += g_nf2[p * CH + c];
      nr2 += g_nr2[p * CH + c];
    }
    const float eps = 1e-8f;
    float nr = fmaxf(sqrtf(nr2), eps);
    float nf = fmaxf(sqrtf(nf2) * (1.f / HH), eps);
    float sim = (dot * (1.f / HH)) / (nr * nf);
    float hidden_c = fmaxf(0.f, (1.f - sim) * 0.5f);
    float token_c = 1.f - teq * (1.f / HH);
    const float invW = 1.f / (float)WW;
    float mrp = trp * invW, mrc = trg * invW;
    float dmass = t6 * invW;
    float dcoh = 0.6f * (tss * invW) + 0.25f * mrp + 0.15f * mrc;
    float pattern_c = 1.f - (0.6f * best + 0.2f * mrp + 0.2f * mrc);
    float contr = fminf(1.f, fmaxf(0.f, 0.2f * hidden_c + 0.2f * token_c + 0.6f * pattern_c));

    out[0 * NPAIR + p] = contr;
    out[1 * NPAIR + p] = s_shift;
    out[2 * NPAIR + p] = sim;
    out[3 * NPAIR + p] = hidden_c;
    out[4 * NPAIR + p] = token_c;
    out[5 * NPAIR + p] = pattern_c;
    out[6 * NPAIR + p] = dmass;
    out[7 * NPAIR + p] = dcoh;
  }
}

extern "C" void kernel_launch(void* const* d_in, const int* in_sizes, int n_in,
                              void* d_out, int out_size) {
  (void)in_sizes; (void)n_in; (void)out_size;
  const float* hidden = (const float*)d_in[0];
  const float* anchor = (const float*)d_in[1];
  const int*   ids    = (const int*)d_in[2];
  const int*   aendp  = (const int*)d_in[3];
  cm_fused<<<NPAIR * CH, 256>>>(hidden, anchor, ids, aendp, (float*)d_out);
}

// round 7
// speedup vs baseline: 1.1060x; 1.1060x over previous
#include <cuda_runtime.h>

// Problem constants (fixed by setup_inputs: B=8,T=4096,D=1024,A=32,S=16,TTL=64)
#define NB_B 8
#define NB_T 4096
#define NB_D 1024
#define NB_A 32
#define SP   16
#define HH   256           // H = max(ttl*4, span*4)
#define WW   (HH - SP + 1) // 241
#define NPAIR (NB_B * NB_A)
#define CH   4             // column chunks (CTAs) per pair
#define CG   64            // float4 groups per chunk (256 floats)
#define NG   (NB_D / 4)    // 256 float4 groups per row

// scratch
__device__ float g_rshift[NPAIR * HH * CH];  // per-(pair,row) chunk partial norms^2
__device__ float g_dot[NPAIR * CH];
__device__ float g_nf2[NPAIR * CH];
__device__ float g_nr2[NPAIR * CH];
__device__ float g_tok[NPAIR * 8];           // best,trp,trg,tss,teq,t6

__constant__ signed char c_alias[64] = {
  -1,-1,-1,-1,-1,-1,-1,-1,-1,-1,-1,
  11,-1,11,-1,-1,11,
  -1,-1,-1,-1,
  21,21,21,
  -1,-1,-1,-1,-1,-1,-1,
  31,31,31,
  -1,-1,-1,-1,-1,-1,-1,
  41,41,41,41,
  -1,-1,-1,-1,-1,-1,
  51,51,51,
  -1,-1,-1,-1,-1,-1,-1,-1,-1,-1
};

// ---- Kernel 1: 1024 streaming CTAs (column slices) + 256 token CTAs ----
__global__ void __launch_bounds__(256, 4) cm_stream(
    const float* __restrict__ hidden,
    const float* __restrict__ anchor,
    const int*   __restrict__ ids,
    const int*   __restrict__ aend)
{
  const int blk  = blockIdx.x;
  const int tid  = threadIdx.x;
  const int lane = tid & 31;
  const int wp   = tid >> 5;

  if (blk < NPAIR * CH) {
    // ================= streaming CTA =================
    const int p     = blk >> 2;
    const int chunk = blk & 3;
    const int b     = p / NB_A;
    const int ae    = aend[p];
    const int start = ae + 1;

    const float4* __restrict__ hb =
        reinterpret_cast<const float4*>(hidden)
        + ((size_t)b * NB_T + start) * NG + chunk * CG;
    const float4* __restrict__ af =
        reinterpret_cast<const float4*>(anchor) + (size_t)p * NG + chunk * CG;

    const float4 a0 = af[lane];
    const float4 a1 = af[lane + 32];
    float4 cs0 = make_float4(0.f,0.f,0.f,0.f);
    float4 cs1 = make_float4(0.f,0.f,0.f,0.f);

    const int row0 = wp * 32;   // warp owns 32 rows
    float* __restrict__ rsh = g_rshift + ((size_t)p * HH) * CH + chunk;

#pragma unroll 1
    for (int it = 0; it < 16; it++) {
      const int r = row0 + it * 2;
      const float4* __restrict__ rp0 = hb + (size_t)r * NG;
      const float4* __restrict__ rp1 = rp0 + NG;
      float4 x0 = rp0[lane];
      float4 y0 = rp0[lane + 32];
      float4 x1 = rp1[lane];
      float4 y1 = rp1[lane + 32];

      cs0.x += x0.x + x1.x; cs0.y += x0.y + x1.y;
      cs0.z += x0.z + x1.z; cs0.w += x0.w + x1.w;
      cs1.x += y0.x + y1.x; cs1.y += y0.y + y1.y;
      cs1.z += y0.z + y1.z; cs1.w += y0.w + y1.w;

      float dx = x0.x - a0.x, dy = x0.y - a0.y, dz = x0.z - a0.z, dw = x0.w - a0.w;
      float v0 = dx*dx + dy*dy + dz*dz + dw*dw;
      dx = y0.x - a1.x; dy = y0.y - a1.y; dz = y0.z - a1.z; dw = y0.w - a1.w;
      v0 += dx*dx + dy*dy + dz*dz + dw*dw;
      dx = x1.x - a0.x; dy = x1.y - a0.y; dz = x1.z - a0.z; dw = x1.w - a0.w;
      float v1 = dx*dx + dy*dy + dz*dz + dw*dw;
      dx = y1.x - a1.x; dy = y1.y - a1.y; dz = y1.z - a1.z; dw = y1.w - a1.w;
      v1 += dx*dx + dy*dy + dz*dz + dw*dw;

#pragma unroll
      for (int o = 16; o; o >>= 1) {
        v0 += __shfl_xor_sync(0xffffffffu, v0, o);
        v1 += __shfl_xor_sync(0xffffffffu, v1, o);
      }
      if (lane < 2) rsh[(r + lane) * CH] = (lane == 0) ? v0 : v1;
    }

    // combine warps' column sums -> chunk scalars
    __shared__ float4 scs[8 * 64];
    __shared__ float  sfin[3 * 8];
    scs[wp * 64 + lane]      = cs0;
    scs[wp * 64 + lane + 32] = cs1;
    __syncthreads();

    if (tid < 64) {
      float4 t = scs[tid];
#pragma unroll
      for (int w = 1; w < 8; w++) {
        float4 u = scs[w * 64 + tid];
        t.x += u.x; t.y += u.y; t.z += u.z; t.w += u.w;
      }
      float4 a = af[tid];
      float dot = a.x*t.x + a.y*t.y + a.z*t.z + a.w*t.w;
      float nf2 = t.x*t.x + t.y*t.y + t.z*t.z + t.w*t.w;
      float nr2 = a.x*a.x + a.y*a.y + a.z*a.z + a.w*a.w;
#pragma unroll
      for (int o = 16; o; o >>= 1) {
        dot += __shfl_xor_sync(0xffffffffu, dot, o);
        nf2 += __shfl_xor_sync(0xffffffffu, nf2, o);
        nr2 += __shfl_xor_sync(0xffffffffu, nr2, o);
      }
      if (lane == 0) {
        sfin[wp * 3 + 0] = dot; sfin[wp * 3 + 1] = nf2; sfin[wp * 3 + 2] = nr2;
      }
    }
    __syncthreads();
    if (tid == 0) {
      g_dot[blk] = sfin[0] + sfin[3];
      g_nf2[blk] = sfin[1] + sfin[4];
      g_nr2[blk] = sfin[2] + sfin[5];
    }
    return;
  }

  // ================= token CTA (one per pair) =================
  const int p = blk - NPAIR * CH;
  const int b = p / NB_A;
  const int ae    = aend[p];
  const int start = ae + 1;

  __shared__ float sred[48];
  __shared__ int   ftok[HH];
  __shared__ int   sp_[SP];
  __shared__ signed char s_alias[64];
  __shared__ int   s_root, s_has, s_atok;
  __shared__ float s_invden;
  __shared__ unsigned long long s_spanmask, s_cmask;

  if (tid < 64) s_alias[tid] = c_alias[tid];
  ftok[tid] = ids[b * NB_T + start + tid];
  if (tid < SP) sp_[tid] = ids[b * NB_T + ae - (SP - 1) + tid];
  if (tid == 0) s_atok = ids[b * NB_T + ae];
  __syncthreads();

  if (tid == 0) {
    int root = -1;
    for (int s = 0; s < SP; s++) {
      int al = s_alias[sp_[s]];
      if (al >= 0) { root = al; break; }
    }
    if (root < 0) {
      int counts[SP]; int maxc = 0;
      for (int s = 0; s < SP; s++) {
        int c2 = 0;
        for (int s2 = 0; s2 < SP; s2++) c2 += (sp_[s2] == sp_[s]);
        counts[s] = c2; if (c2 > maxc) maxc = c2;
      }
      int mode = 64;
      for (int s = 0; s < SP; s++)
        if (counts[s] == maxc && sp_[s] < mode) mode = sp_[s];
      root = mode;
    }
    unsigned long long smask = 0ull; int den = 0;
    for (int s = 0; s < SP; s++) {
      bool first = true;
      for (int s2 = 0; s2 < s; s2++)
        if (sp_[s2] == sp_[s]) { first = false; break; }
      if (first) { den++; smask |= (1ull << sp_[s]); }
    }
    s_root = root;
    s_spanmask = smask;
    s_invden = 1.f / (float)den;
    s_has = (root == 11 || root == 21 || root == 31 || root == 41 || root == 51) ? 1 : 0;
    unsigned long long cm = 0ull;
    switch (root) {
      case 11: cm = (1ull<<11)|(1ull<<13)|(1ull<<16); break;
      case 21: cm = (1ull<<14)|(1ull<<15)|(1ull<<21)|(1ull<<22)|(1ull<<23); break;
      case 31: cm = (1ull<<15)|(1ull<<31)|(1ull<<32)|(1ull<<33); break;
      case 41: cm = (1ull<<41)|(1ull<<42)|(1ull<<43)|(1ull<<44); break;
      case 51: cm = (1ull<<15)|(1ull<<51)|(1ull<<52)|(1ull<<53); break;
      default: break;
    }
    s_cmask = cm;
  }
  __syncthreads();

  int myeq = (ftok[tid] == s_atok) ? 1 : 0;

  float sims = -1e30f, rootp = 0.f, regime = 0.f, ssum = 0.f;
  int c06 = 0;
  if (tid < WW) {
    const int root = s_root;
    const unsigned long long cmask = s_cmask;
    float exact = 0.f, positional = 0.f;
    unsigned long long wmask = 0ull;
    int c_rp = 0, c_al = 0, c_hd = 0;
#pragma unroll
    for (int s = 0; s < SP; s++) {
      int t = ftok[tid + s];
      wmask |= (1ull << t);
      if (t == sp_[s]) { exact += 1.f; positional += (1.0f - 0.04f * (float)s); }
      c_rp += (t == root);
      c_al += ((int)s_alias[t] == root);
      c_hd += (int)((cmask >> t) & 1ull);
    }
    exact *= (1.f / 16.f);
    positional *= (1.f / 11.2f);
    float overlap = (float)__popcll(wmask & s_spanmask) * s_invden;
    rootp = (float)c_rp * (1.f / 16.f);
    float aliasc = (float)c_al * (1.f / 16.f);
    float hard   = (float)c_hd * (1.f / 16.f);
    regime = s_has ? (0.55f * hard  + 0.2f * overlap + 0.15f * aliasc + 0.1f  * rootp)
                   : (0.45f * exact + 0.3f * overlap + 0.1f  * aliasc + 0.15f * rootp);
    float sv = 0.25f * exact + 0.15f * overlap + 0.35f * positional + 0.25f * regime;
    sims = sv; ssum = sv;
    c06 = (sv >= 0.6f) ? 1 : 0;
  }

  float msims = sims, srp = rootp, srg = regime, sss = ssum;
  int ceq = myeq, c6 = c06;
#pragma unroll
  for (int o = 16; o; o >>= 1) {
    msims = fmaxf(msims, __shfl_xor_sync(0xffffffffu, msims, o));
    srp += __shfl_xor_sync(0xffffffffu, srp, o);
    srg += __shfl_xor_sync(0xffffffffu, srg, o);
    sss += __shfl_xor_sync(0xffffffffu, sss, o);
    ceq += __shfl_xor_sync(0xffffffffu, ceq, o);
    c6  += __shfl_xor_sync(0xffffffffu, c6, o);
  }
  if (lane == 0) {
    sred[wp]      = msims;
    sred[8 + wp]  = srp;
    sred[16 + wp] = srg;
    sred[24 + wp] = sss;
    sred[32 + wp] = (float)ceq;
    sred[40 + wp] = (float)c6;
  }
  __syncthreads();

  if (tid == 0) {
    float best = -1e30f, trp = 0.f, trg = 0.f, tss = 0.f, teq = 0.f, t6 = 0.f;
    for (int k = 0; k < 8; k++) {
      best = fmaxf(best, sred[k]);
      trp += sred[8 + k]; trg += sred[16 + k]; tss += sred[24 + k];
      teq += sred[32 + k]; t6 += sred[40 + k];
    }
    g_tok[p * 8 + 0] = best;
    g_tok[p * 8 + 1] = trp;
    g_tok[p * 8 + 2] = trg;
    g_tok[p * 8 + 3] = tss;
    g_tok[p * 8 + 4] = teq;
    g_tok[p * 8 + 5] = t6;
  }
}

// ---- Kernel 2: tiny finalizer, one CTA per pair ----
__global__ void __launch_bounds__(256, 8) cm_final(float* __restrict__ out)
{
  const int p    = blockIdx.x;
  const int tid  = threadIdx.x;
  const int lane = tid & 31;
  const int wp   = tid >> 5;

  __shared__ float ssh[8];

  // per-row norm: thread tid owns row tid
  float4 rp4 = reinterpret_cast<const float4*>(g_rshift)[p * HH + tid];
  float rn = sqrtf(rp4.x + rp4.y + rp4.z + rp4.w);
#pragma unroll
  for (int o = 16; o; o >>= 1) rn += __shfl_xor_sync(0xffffffffu, rn, o);
  if (lane == 0) ssh[wp] = rn;
  __syncthreads();

  if (tid == 0) {
    float sh = 0.f;
#pragma unroll
    for (int k = 0; k < 8; k++) sh += ssh[k];
    float shift = sh * (1.f / HH);

    float dot = 0.f, nf2 = 0.f, nr2 = 0.f;
#pragma unroll
    for (int c = 0; c < CH; c++) {
      dot += g_dot[p * CH + c];
      nf2 += g_nf2[p * CH + c];
      nr2 += g_nr2[p * CH + c];
    }
    float best = g_tok[p * 8 + 0];
    float trp  = g_tok[p * 8 + 1];
    float trg  = g_tok[p * 8 + 2];
    float tss  = g_tok[p * 8 + 3];
    float teq  = g_tok[p * 8 + 4];
    float t6   = g_tok[p * 8 + 5];

    const float eps = 1e-8f;
    float nr = fmaxf(sqrtf(nr2), eps);
    float nf = fmaxf(sqrtf(nf2) * (1.f / HH), eps);
    float sim = (dot * (1.f / HH)) / (nr * nf);
    float hidden_c = fmaxf(0.f, (1.f - sim) * 0.5f);
    float token_c = 1.f - teq * (1.f / HH);
    const float invW = 1.f / (float)WW;
    float mrp = trp * invW, mrc = trg * invW;
    float dmass = t6 * invW;
    float dcoh = 0.6f * (tss * invW) + 0.25f * mrp + 0.15f * mrc;
    float pattern_c = 1.f - (0.6f * best + 0.2f * mrp + 0.2f * mrc);
    float contr = fminf(1.f, fmaxf(0.f, 0.2f * hidden_c + 0.2f * token_c + 0.6f * pattern_c));

    out[0 * NPAIR + p] = contr;
    out[1 * NPAIR + p] = shift;
    out[2 * NPAIR + p] = sim;
    out[3 * NPAIR + p] = hidden_c;
    out[4 * NPAIR + p] = token_c;
    out[5 * NPAIR + p] = pattern_c;
    out[6 * NPAIR + p] = dmass;
    out[7 * NPAIR + p] = dcoh;
  }
}

extern "C" void kernel_launch(void* const* d_in, const int* in_sizes, int n_in,
                              void* d_out, int out_size) {
  (void)in_sizes; (void)n_in; (void)out_size;
  const float* hidden = (const float*)d_in[0];
  const float* anchor = (const float*)d_in[1];
  const int*   ids    = (const int*)d_in[2];
  const int*   aendp  = (const int*)d_in[3];
  cm_stream<<<NPAIR * CH + NPAIR, 256>>>(hidden, anchor, ids, aendp);
  cm_final <<<NPAIR, 256>>>((float*)d_out);
}

// round 10
// speedup vs baseline: 1.1473x; 1.0373x over previous
#include <cuda_runtime.h>

// Problem constants (fixed by setup_inputs: B=8,T=4096,D=1024,A=32,S=16,TTL=64)
#define NB_B 8
#define NB_T 4096
#define NB_D 1024
#define NB_A 32
#define SP   16
#define HH   256           // H = max(ttl*4, span*4)
#define WW   (HH - SP + 1) // 241
#define NPAIR (NB_B * NB_A)
#define CH   4             // column chunks (CTAs) per pair
#define CG   64            // float4 groups per chunk (256 floats)
#define NG   (NB_D / 4)    // 256 float4 groups per row

// scratch
__device__ float g_rshift[NPAIR * HH * CH];  // per-(pair,row) chunk partial norms^2
__device__ float g_dot[NPAIR * CH];
__device__ float g_nf2[NPAIR * CH];
__device__ float g_nr2[NPAIR * CH];
__device__ float g_tok[NPAIR * 8];           // best,trp,trg,tss,teq,t6

__constant__ signed char c_alias[64] = {
  -1,-1,-1,-1,-1,-1,-1,-1,-1,-1,-1,
  11,-1,11,-1,-1,11,
  -1,-1,-1,-1,
  21,21,21,
  -1,-1,-1,-1,-1,-1,-1,
  31,31,31,
  -1,-1,-1,-1,-1,-1,-1,
  41,41,41,41,
  -1,-1,-1,-1,-1,-1,
  51,51,51,
  -1,-1,-1,-1,-1,-1,-1,-1,-1,-1
};

// ---- Kernel 1: 1024 streaming CTAs (column slices) + 256 token CTAs ----
__global__ void __launch_bounds__(256, 5) cm_stream(
    const float* __restrict__ hidden,
    const float* __restrict__ anchor,
    const int*   __restrict__ ids,
    const int*   __restrict__ aend)
{
  const int blk  = blockIdx.x;
  const int tid  = threadIdx.x;
  const int lane = tid & 31;
  const int wp   = tid >> 5;

  if (blk < NPAIR * CH) {
    // ================= streaming CTA =================
    const int p     = blk >> 2;
    const int chunk = blk & 3;
    const int b     = p / NB_A;
    const int ae    = aend[p];
    const int start = ae + 1;

    // srow: per-lane row-norm partials [lane][row], padded stride 258.
    // scs (column-sum combine) is overlapped onto the same storage — its use
    // begins only after all srow reads are done (guarded by __syncthreads()).
    __shared__ float srow[32 * 258];     // 33 KB
    float4* scs = reinterpret_cast<float4*>(srow);   // needs 8*64*16 B = 8.25K floats
    __shared__ float  sfin[3 * 8];

    const float4* __restrict__ hb =
        reinterpret_cast<const float4*>(hidden)
        + ((size_t)b * NB_T + start) * NG + chunk * CG;
    const float4* __restrict__ af =
        reinterpret_cast<const float4*>(anchor) + (size_t)p * NG + chunk * CG;

    const float4 a0 = af[lane];
    const float4 a1 = af[lane + 32];
    float4 cs0 = make_float4(0.f,0.f,0.f,0.f);
    float4 cs1 = make_float4(0.f,0.f,0.f,0.f);

    const int row0 = wp * 32;   // warp owns 32 rows
    float* __restrict__ myrow = srow + lane * 258;

#pragma unroll 1
    for (int it = 0; it < 16; it++) {
      const int r = row0 + it * 2;
      const float4* __restrict__ rp0 = hb + (size_t)r * NG;
      const float4* __restrict__ rp1 = rp0 + NG;
      float4 x0 = rp0[lane];
      float4 y0 = rp0[lane + 32];
      float4 x1 = rp1[lane];
      float4 y1 = rp1[lane + 32];

      cs0.x += x0.x + x1.x; cs0.y += x0.y + x1.y;
      cs0.z += x0.z + x1.z; cs0.w += x0.w + x1.w;
      cs1.x += y0.x + y1.x; cs1.y += y0.y + y1.y;
      cs1.z += y0.z + y1.z; cs1.w += y0.w + y1.w;

      float dx = x0.x - a0.x, dy = x0.y - a0.y, dz = x0.z - a0.z, dw = x0.w - a0.w;
      float v0 = dx*dx + dy*dy + dz*dz + dw*dw;
      dx = y0.x - a1.x; dy = y0.y - a1.y; dz = y0.z - a1.z; dw = y0.w - a1.w;
      v0 += dx*dx + dy*dy + dz*dz + dw*dw;
      dx = x1.x - a0.x; dy = x1.y - a0.y; dz = x1.z - a0.z; dw = x1.w - a0.w;
      float v1 = dx*dx + dy*dy + dz*dz + dw*dw;
      dx = y1.x - a1.x; dy = y1.y - a1.y; dz = y1.z - a1.z; dw = y1.w - a1.w;
      v1 += dx*dx + dy*dy + dz*dz + dw*dw;

      // one 64-bit store; (lane*258 + r)*4 is 8B-aligned since r is even
      *reinterpret_cast<float2*>(myrow + r) = make_float2(v0, v1);
    }
    __syncthreads();

    // row-sum transpose: thread t reduces row t's 32 lane-partials (conflict-free)
    float rowsum = 0.f;
#pragma unroll
    for (int l = 0; l < 32; l++) rowsum += srow[l * 258 + tid];
    g_rshift[((size_t)p * HH + tid) * CH + chunk] = rowsum;

    __syncthreads();   // all srow reads complete before scs (aliased) is written

    // combine warps' column sums -> chunk scalars
    scs[wp * 64 + lane]      = cs0;
    scs[wp * 64 + lane + 32] = cs1;
    __syncthreads();

    if (tid < 64) {
      float4 t = scs[tid];
#pragma unroll
      for (int w = 1; w < 8; w++) {
        float4 u = scs[w * 64 + tid];
        t.x += u.x; t.y += u.y; t.z += u.z; t.w += u.w;
      }
      float4 a = af[tid];
      float dot = a.x*t.x + a.y*t.y + a.z*t.z + a.w*t.w;
      float nf2 = t.x*t.x + t.y*t.y + t.z*t.z + t.w*t.w;
      float nr2 = a.x*a.x + a.y*a.y + a.z*a.z + a.w*a.w;
#pragma unroll
      for (int o = 16; o; o >>= 1) {
        dot += __shfl_xor_sync(0xffffffffu, dot, o);
        nf2 += __shfl_xor_sync(0xffffffffu, nf2, o);
        nr2 += __shfl_xor_sync(0xffffffffu, nr2, o);
      }
      if (lane == 0) {
        sfin[wp * 3 + 0] = dot; sfin[wp * 3 + 1] = nf2; sfin[wp * 3 + 2] = nr2;
      }
    }
    __syncthreads();
    if (tid == 0) {
      g_dot[blk] = sfin[0] + sfin[3];
      g_nf2[blk] = sfin[1] + sfin[4];
      g_nr2[blk] = sfin[2] + sfin[5];
    }
    return;
  }

  // ================= token CTA (one per pair) =================
  const int p = blk - NPAIR * CH;
  const int b = p / NB_A;
  const int ae    = aend[p];
  const int start = ae + 1;

  __shared__ float sred[48];
  __shared__ int   ftok[HH];
  __shared__ int   sp_[SP];
  __shared__ signed char s_alias[64];
  __shared__ int   s_root, s_has, s_atok;
  __shared__ float s_invden;
  __shared__ unsigned long long s_spanmask, s_cmask;

  if (tid < 64) s_alias[tid] = c_alias[tid];
  ftok[tid] = ids[b * NB_T + start + tid];
  if (tid < SP) sp_[tid] = ids[b * NB_T + ae - (SP - 1) + tid];
  if (tid == 0) s_atok = ids[b * NB_T + ae];
  __syncthreads();

  if (tid == 0) {
    int root = -1;
    for (int s = 0; s < SP; s++) {
      int al = s_alias[sp_[s]];
      if (al >= 0) { root = al; break; }
    }
    if (root < 0) {
      int counts[SP]; int maxc = 0;
      for (int s = 0; s < SP; s++) {
        int c2 = 0;
        for (int s2 = 0; s2 < SP; s2++) c2 += (sp_[s2] == sp_[s]);
        counts[s] = c2; if (c2 > maxc) maxc = c2;
      }
      int mode = 64;
      for (int s = 0; s < SP; s++)
        if (counts[s] == maxc && sp_[s] < mode) mode = sp_[s];
      root = mode;
    }
    unsigned long long smask = 0ull; int den = 0;
    for (int s = 0; s < SP; s++) {
      bool first = true;
      for (int s2 = 0; s2 < s; s2++)
        if (sp_[s2] == sp_[s]) { first = false; break; }
      if (first) { den++; smask |= (1ull << sp_[s]); }
    }
    s_root = root;
    s_spanmask = smask;
    s_invden = 1.f / (float)den;
    s_has = (root == 11 || root == 21 || root == 31 || root == 41 || root == 51) ? 1 : 0;
    unsigned long long cm = 0ull;
    switch (root) {
      case 11: cm = (1ull<<11)|(1ull<<13)|(1ull<<16); break;
      case 21: cm = (1ull<<14)|(1ull<<15)|(1ull<<21)|(1ull<<22)|(1ull<<23); break;
      case 31: cm = (1ull<<15)|(1ull<<31)|(1ull<<32)|(1ull<<33); break;
      case 41: cm = (1ull<<41)|(1ull<<42)|(1ull<<43)|(1ull<<44); break;
      case 51: cm = (1ull<<15)|(1ull<<51)|(1ull<<52)|(1ull<<53); break;
      default: break;
    }
    s_cmask = cm;
  }
  __syncthreads();

  int myeq = (ftok[tid] == s_atok) ? 1 : 0;

  float sims = -1e30f, rootp = 0.f, regime = 0.f, ssum = 0.f;
  int c06 = 0;
  if (tid < WW) {
    const int root = s_root;
    const unsigned long long cmask = s_cmask;
    float exact = 0.f, positional = 0.f;
    unsigned long long wmask = 0ull;
    int c_rp = 0, c_al = 0, c_hd = 0;
#pragma unroll
    for (int s = 0; s < SP; s++) {
      int t = ftok[tid + s];
      wmask |= (1ull << t);
      if (t == sp_[s]) { exact += 1.f; positional += (1.0f - 0.04f * (float)s); }
      c_rp += (t == root);
      c_al += ((int)s_alias[t] == root);
      c_hd += (int)((cmask >> t) & 1ull);
    }
    exact *= (1.f / 16.f);
    positional *= (1.f / 11.2f);
    float overlap = (float)__popcll(wmask & s_spanmask) * s_invden;
    rootp = (float)c_rp * (1.f / 16.f);
    float aliasc = (float)c_al * (1.f / 16.f);
    float hard   = (float)c_hd * (1.f / 16.f);
    regime = s_has ? (0.55f * hard  + 0.2f * overlap + 0.15f * aliasc + 0.1f  * rootp)
                   : (0.45f * exact + 0.3f * overlap + 0.1f  * aliasc + 0.15f * rootp);
    float sv = 0.25f * exact + 0.15f * overlap + 0.35f * positional + 0.25f * regime;
    sims = sv; ssum = sv;
    c06 = (sv >= 0.6f) ? 1 : 0;
  }

  float msims = sims, srp = rootp, srg = regime, sss = ssum;
  int ceq = myeq, c6 = c06;
#pragma unroll
  for (int o = 16; o; o >>= 1) {
    msims = fmaxf(msims, __shfl_xor_sync(0xffffffffu, msims, o));
    srp += __shfl_xor_sync(0xffffffffu, srp, o);
    srg += __shfl_xor_sync(0xffffffffu, srg, o);
    sss += __shfl_xor_sync(0xffffffffu, sss, o);
    ceq += __shfl_xor_sync(0xffffffffu, ceq, o);
    c6  += __shfl_xor_sync(0xffffffffu, c6, o);
  }
  if (lane == 0) {
    sred[wp]      = msims;
    sred[8 + wp]  = srp;
    sred[16 + wp] = srg;
    sred[24 + wp] = sss;
    sred[32 + wp] = (float)ceq;
    sred[40 + wp] = (float)c6;
  }
  __syncthreads();

  if (tid == 0) {
    float best = -1e30f, trp = 0.f, trg = 0.f, tss = 0.f, teq = 0.f, t6 = 0.f;
    for (int k = 0; k < 8; k++) {
      best = fmaxf(best, sred[k]);
      trp += sred[8 + k]; trg += sred[16 + k]; tss += sred[24 + k];
      teq += sred[32 + k]; t6 += sred[40 + k];
    }
    g_tok[p * 8 + 0] = best;
    g_tok[p * 8 + 1] = trp;
    g_tok[p * 8 + 2] = trg;
    g_tok[p * 8 + 3] = tss;
    g_tok[p * 8 + 4] = teq;
    g_tok[p * 8 + 5] = t6;
  }
}

// ---- Kernel 2: tiny finalizer, one CTA per pair ----
__global__ void __launch_bounds__(256, 8) cm_final(float* __restrict__ out)
{
  const int p    = blockIdx.x;
  const int tid  = threadIdx.x;
  const int lane = tid & 31;
  const int wp   = tid >> 5;

  __shared__ float ssh[8];

  // per-row norm: thread tid owns row tid
  float4 rp4 = reinterpret_cast<const float4*>(g_rshift)[p * HH + tid];
  float rn = sqrtf(rp4.x + rp4.y + rp4.z + rp4.w);
#pragma unroll
  for (int o = 16; o; o >>= 1) rn += __shfl_xor_sync(0xffffffffu, rn, o);
  if (lane == 0) ssh[wp] = rn;
  __syncthreads();

  if (tid == 0) {
    float sh = 0.f;
#pragma unroll
    for (int k = 0; k < 8; k++) sh += ssh[k];
    float shift = sh * (1.f / HH);

    float dot = 0.f, nf2 = 0.f, nr2 = 0.f;
#pragma unroll
    for (int c = 0; c < CH; c++) {
      dot += g_dot[p * CH + c];
      nf2 += g_nf2[p * CH + c];
      nr2 += g_nr2[p * CH + c];
    }
    float best = g_tok[p * 8 + 0];
    float trp  = g_tok[p * 8 + 1];
    float trg  = g_tok[p * 8 + 2];
    float tss  = g_tok[p * 8 + 3];
    float teq  = g_tok[p * 8 + 4];
    float t6   = g_tok[p * 8 + 5];

    const float eps = 1e-8f;
    float nr = fmaxf(sqrtf(nr2), eps);
    float nf = fmaxf(sqrtf(nf2) * (1.f / HH), eps);
    float sim = (dot * (1.f / HH)) / (nr * nf);
    float hidden_c = fmaxf(0.f, (1.f - sim) * 0.5f);
    float token_c = 1.f - teq * (1.f / HH);
    const float invW = 1.f / (float)WW;
    float mrp = trp * invW, mrc = trg * invW;
    float dmass = t6 * invW;
    float dcoh = 0.6f * (tss * invW) + 0.25f * mrp + 0.15f * mrc;
    float pattern_c = 1.f - (0.6f * best + 0.2f * mrp + 0.2f * mrc);
    float contr = fminf(1.f, fmaxf(0.f, 0.2f * hidden_c + 0.2f * token_c + 0.6f * pattern_c));

    out[0 * NPAIR + p] = contr;
    out[1 * NPAIR + p] = shift;
    out[2 * NPAIR + p] = sim;
    out[3 * NPAIR + p] = hidden_c;
    out[4 * NPAIR + p] = token_c;
    out[5 * NPAIR + p] = pattern_c;
    out[6 * NPAIR + p] = dmass;
    out[7 * NPAIR + p] = dcoh;
  }
}

extern "C" void kernel_launch(void* const* d_in, const int* in_sizes, int n_in,
                              void* d_out, int out_size) {
  (void)in_sizes; (void)n_in; (void)out_size;
  const float* hidden = (const float*)d_in[0];
  const float* anchor = (const float*)d_in[1];
  const int*   ids    = (const int*)d_in[2];
  const int*   aendp  = (const int*)d_in[3];
  cm_stream<<<NPAIR * CH + NPAIR, 256>>>(hidden, anchor, ids, aendp);
  cm_final <<<NPAIR, 256>>>((float*)d_out);
}

// round 11
// speedup vs baseline: 1.1526x; 1.0047x over previous
#include <cuda_runtime.h>

// Problem constants (fixed by setup_inputs: B=8,T=4096,D=1024,A=32,S=16,TTL=64)
#define NB_B 8
#define NB_T 4096
#define NB_D 1024
#define NB_A 32
#define SP   16
#define HH   256           // H = max(ttl*4, span*4)
#define WW   (HH - SP + 1) // 241
#define NPAIR (NB_B * NB_A)
#define CH   4             // column chunks (CTAs) per pair
#define CG   64            // float4 groups per chunk (256 floats)
#define NG   (NB_D / 4)    // 256 float4 groups per row

// scratch
__device__ float g_rshift[NPAIR * HH * CH];  // per-(pair,row) chunk partial norms^2
__device__ float g_dot[NPAIR * CH];
__device__ float g_nf2[NPAIR * CH];
__device__ float g_nr2[NPAIR * CH];
__device__ unsigned int g_cnt[NPAIR];        // zero-init; reset by finalizer

__constant__ signed char c_alias[64] = {
  -1,-1,-1,-1,-1,-1,-1,-1,-1,-1,-1,
  11,-1,11,-1,-1,11,
  -1,-1,-1,-1,
  21,21,21,
  -1,-1,-1,-1,-1,-1,-1,
  31,31,31,
  -1,-1,-1,-1,-1,-1,-1,
  41,41,41,41,
  -1,-1,-1,-1,-1,-1,
  51,51,51,
  -1,-1,-1,-1,-1,-1,-1,-1,-1,-1
};

// ---- 1024 streaming CTAs (column slices) + 256 token/finalizer CTAs ----
__global__ void __launch_bounds__(256, 5) cm_stream(
    const float* __restrict__ hidden,
    const float* __restrict__ anchor,
    const int*   __restrict__ ids,
    const int*   __restrict__ aend,
    float*       __restrict__ out)
{
  const int blk  = blockIdx.x;
  const int tid  = threadIdx.x;
  const int lane = tid & 31;
  const int wp   = tid >> 5;

  if (blk < NPAIR * CH) {
    // ================= streaming CTA =================
    const int p     = blk >> 2;
    const int chunk = blk & 3;
    const int b     = p / NB_A;
    const int ae    = aend[p];
    const int start = ae + 1;

    // srow: per-lane row-norm partials [lane][row], padded stride 258.
    // scs (column-sum combine) is overlapped onto the same storage.
    __shared__ float srow[32 * 258];     // 33 KB
    float4* scs = reinterpret_cast<float4*>(srow);
    __shared__ float  sfin[3 * 8];

    const float4* __restrict__ hb =
        reinterpret_cast<const float4*>(hidden)
        + ((size_t)b * NB_T + start) * NG + chunk * CG;
    const float4* __restrict__ af =
        reinterpret_cast<const float4*>(anchor) + (size_t)p * NG + chunk * CG;

    const float4 a0 = af[lane];
    const float4 a1 = af[lane + 32];
    float4 cs0 = make_float4(0.f,0.f,0.f,0.f);
    float4 cs1 = make_float4(0.f,0.f,0.f,0.f);

    const int row0 = wp * 32;   // warp owns 32 rows
    float* __restrict__ myrow = srow + lane * 258;

#pragma unroll 1
    for (int it = 0; it < 16; it++) {
      const int r = row0 + it * 2;
      const float4* __restrict__ rp0 = hb + (size_t)r * NG;
      const float4* __restrict__ rp1 = rp0 + NG;
      float4 x0 = rp0[lane];
      float4 y0 = rp0[lane + 32];
      float4 x1 = rp1[lane];
      float4 y1 = rp1[lane + 32];

      cs0.x += x0.x + x1.x; cs0.y += x0.y + x1.y;
      cs0.z += x0.z + x1.z; cs0.w += x0.w + x1.w;
      cs1.x += y0.x + y1.x; cs1.y += y0.y + y1.y;
      cs1.z += y0.z + y1.z; cs1.w += y0.w + y1.w;

      float dx = x0.x - a0.x, dy = x0.y - a0.y, dz = x0.z - a0.z, dw = x0.w - a0.w;
      float v0 = dx*dx + dy*dy + dz*dz + dw*dw;
      dx = y0.x - a1.x; dy = y0.y - a1.y; dz = y0.z - a1.z; dw = y0.w - a1.w;
      v0 += dx*dx + dy*dy + dz*dz + dw*dw;
      dx = x1.x - a0.x; dy = x1.y - a0.y; dz = x1.z - a0.z; dw = x1.w - a0.w;
      float v1 = dx*dx + dy*dy + dz*dz + dw*dw;
      dx = y1.x - a1.x; dy = y1.y - a1.y; dz = y1.z - a1.z; dw = y1.w - a1.w;
      v1 += dx*dx + dy*dy + dz*dz + dw*dw;

      *reinterpret_cast<float2*>(myrow + r) = make_float2(v0, v1);
    }
    __syncthreads();

    // row-sum transpose: thread t reduces row t's 32 lane-partials (conflict-free)
    float rowsum = 0.f;
#pragma unroll
    for (int l = 0; l < 32; l++) rowsum += srow[l * 258 + tid];
    g_rshift[((size_t)p * HH + tid) * CH + chunk] = rowsum;

    __syncthreads();   // srow reads complete before scs (aliased) is written

    // combine warps' column sums -> chunk scalars
    scs[wp * 64 + lane]      = cs0;
    scs[wp * 64 + lane + 32] = cs1;
    __syncthreads();

    if (tid < 64) {
      float4 t = scs[tid];
#pragma unroll
      for (int w = 1; w < 8; w++) {
        float4 u = scs[w * 64 + tid];
        t.x += u.x; t.y += u.y; t.z += u.z; t.w += u.w;
      }
      float4 a = af[tid];
      float dot = a.x*t.x + a.y*t.y + a.z*t.z + a.w*t.w;
      float nf2 = t.x*t.x + t.y*t.y + t.z*t.z + t.w*t.w;
      float nr2 = a.x*a.x + a.y*a.y + a.z*a.z + a.w*a.w;
#pragma unroll
      for (int o = 16; o; o >>= 1) {
        dot += __shfl_xor_sync(0xffffffffu, dot, o);
        nf2 += __shfl_xor_sync(0xffffffffu, nf2, o);
        nr2 += __shfl_xor_sync(0xffffffffu, nr2, o);
      }
      if (lane == 0) {
        sfin[wp * 3 + 0] = dot; sfin[wp * 3 + 1] = nf2; sfin[wp * 3 + 2] = nr2;
      }
    }
    __syncthreads();
    if (tid == 0) {
      g_dot[blk] = sfin[0] + sfin[3];
      g_nf2[blk] = sfin[1] + sfin[4];
      g_nr2[blk] = sfin[2] + sfin[5];
      // release-publish this chunk (no MEMBAR/IVALL; ordering at L2)
      asm volatile("red.release.gpu.global.add.u32 [%0], 1;"
                   :: "l"(&g_cnt[p]) : "memory");
    }
    return;
  }

  // ================= token + finalizer CTA (one per pair) =================
  const int p = blk - NPAIR * CH;
  const int b = p / NB_A;
  const int ae    = aend[p];
  const int start = ae + 1;

  __shared__ float sred[56];
  __shared__ int   ftok[HH];
  __shared__ int   sp_[SP];
  __shared__ signed char s_alias[64];
  __shared__ int   s_root, s_has, s_atok;
  __shared__ float s_invden;
  __shared__ unsigned long long s_spanmask, s_cmask;

  if (tid < 64) s_alias[tid] = c_alias[tid];
  ftok[tid] = ids[b * NB_T + start + tid];
  if (tid < SP) sp_[tid] = ids[b * NB_T + ae - (SP - 1) + tid];
  if (tid == 0) s_atok = ids[b * NB_T + ae];
  __syncthreads();

  if (tid == 0) {
    int root = -1;
    for (int s = 0; s < SP; s++) {
      int al = s_alias[sp_[s]];
      if (al >= 0) { root = al; break; }
    }
    if (root < 0) {
      int counts[SP]; int maxc = 0;
      for (int s = 0; s < SP; s++) {
        int c2 = 0;
        for (int s2 = 0; s2 < SP; s2++) c2 += (sp_[s2] == sp_[s]);
        counts[s] = c2; if (c2 > maxc) maxc = c2;
      }
      int mode = 64;
      for (int s = 0; s < SP; s++)
        if (counts[s] == maxc && sp_[s] < mode) mode = sp_[s];
      root = mode;
    }
    unsigned long long smask = 0ull; int den = 0;
    for (int s = 0; s < SP; s++) {
      bool first = true;
      for (int s2 = 0; s2 < s; s2++)
        if (sp_[s2] == sp_[s]) { first = false; break; }
      if (first) { den++; smask |= (1ull << sp_[s]); }
    }
    s_root = root;
    s_spanmask = smask;
    s_invden = 1.f / (float)den;
    s_has = (root == 11 || root == 21 || root == 31 || root == 41 || root == 51) ? 1 : 0;
    unsigned long long cm = 0ull;
    switch (root) {
      case 11: cm = (1ull<<11)|(1ull<<13)|(1ull<<16); break;
      case 21: cm = (1ull<<14)|(1ull<<15)|(1ull<<21)|(1ull<<22)|(1ull<<23); break;
      case 31: cm = (1ull<<15)|(1ull<<31)|(1ull<<32)|(1ull<<33); break;
      case 41: cm = (1ull<<41)|(1ull<<42)|(1ull<<43)|(1ull<<44); break;
      case 51: cm = (1ull<<15)|(1ull<<51)|(1ull<<52)|(1ull<<53); break;
      default: break;
    }
    s_cmask = cm;
  }
  __syncthreads();

  int myeq = (ftok[tid] == s_atok) ? 1 : 0;

  float sims = -1e30f, rootp = 0.f, regime = 0.f, ssum = 0.f;
  int c06 = 0;
  if (tid < WW) {
    const int root = s_root;
    const unsigned long long cmask = s_cmask;
    float exact = 0.f, positional = 0.f;
    unsigned long long wmask = 0ull;
    int c_rp = 0, c_al = 0, c_hd = 0;
#pragma unroll
    for (int s = 0; s < SP; s++) {
      int t = ftok[tid + s];
      wmask |= (1ull << t);
      if (t == sp_[s]) { exact += 1.f; positional += (1.0f - 0.04f * (float)s); }
      c_rp += (t == root);
      c_al += ((int)s_alias[t] == root);
      c_hd += (int)((cmask >> t) & 1ull);
    }
    exact *= (1.f / 16.f);
    positional *= (1.f / 11.2f);
    float overlap = (float)__popcll(wmask & s_spanmask) * s_invden;
    rootp = (float)c_rp * (1.f / 16.f);
    float aliasc = (float)c_al * (1.f / 16.f);
    float hard   = (float)c_hd * (1.f / 16.f);
    regime = s_has ? (0.55f * hard  + 0.2f * overlap + 0.15f * aliasc + 0.1f  * rootp)
                   : (0.45f * exact + 0.3f * overlap + 0.1f  * aliasc + 0.15f * rootp);
    float sv = 0.25f * exact + 0.15f * overlap + 0.35f * positional + 0.25f * regime;
    sims = sv; ssum = sv;
    c06 = (sv >= 0.6f) ? 1 : 0;
  }

  float msims = sims, srp = rootp, srg = regime, sss = ssum;
  int ceq = myeq, c6 = c06;
#pragma unroll
  for (int o = 16; o; o >>= 1) {
    msims = fmaxf(msims, __shfl_xor_sync(0xffffffffu, msims, o));
    srp += __shfl_xor_sync(0xffffffffu, srp, o);
    srg += __shfl_xor_sync(0xffffffffu, srg, o);
    sss += __shfl_xor_sync(0xffffffffu, sss, o);
    ceq += __shfl_xor_sync(0xffffffffu, ceq, o);
    c6  += __shfl_xor_sync(0xffffffffu, c6, o);
  }
  if (lane == 0) {
    sred[wp]      = msims;
    sred[8 + wp]  = srp;
    sred[16 + wp] = srg;
    sred[24 + wp] = sss;
    sred[32 + wp] = (float)ceq;
    sred[40 + wp] = (float)c6;
  }
  __syncthreads();

  // token scalars (held in tid0 registers across the wait)
  float best = -1e30f, trp = 0.f, trg = 0.f, tss = 0.f, teq = 0.f, t6 = 0.f;
  if (tid == 0) {
    for (int k = 0; k < 8; k++) {
      best = fmaxf(best, sred[k]);
      trp += sred[8 + k]; trg += sred[16 + k]; tss += sred[24 + k];
      teq += sred[32 + k]; t6 += sred[40 + k];
    }
    // acquire-spin until this pair's 4 streaming chunks have published
    unsigned int v;
    do {
      asm volatile("ld.acquire.gpu.global.u32 %0, [%1];"
                   : "=r"(v) : "l"(&g_cnt[p]) : "memory");
      if (v == CH) break;
      __nanosleep(64);
    } while (1);
    g_cnt[p] = 0;   // reset for next graph replay (kernel boundary orders it)
  }
  __syncthreads();

  // row-norm finalization: thread tid owns row tid
  float4 rp4 = reinterpret_cast<const float4*>(g_rshift)[p * HH + tid];
  float rn = sqrtf(rp4.x + rp4.y + rp4.z + rp4.w);
#pragma unroll
  for (int o = 16; o; o >>= 1) rn += __shfl_xor_sync(0xffffffffu, rn, o);
  if (lane == 0) sred[48 + wp] = rn;
  __syncthreads();

  if (tid == 0) {
    float sh = 0.f;
#pragma unroll
    for (int k = 0; k < 8; k++) sh += sred[48 + k];
    float shift = sh * (1.f / HH);

    float dot = 0.f, nf2 = 0.f, nr2 = 0.f;
#pragma unroll
    for (int c = 0; c < CH; c++) {
      dot += g_dot[p * CH + c];
      nf2 += g_nf2[p * CH + c];
      nr2 += g_nr2[p * CH + c];
    }
    const float eps = 1e-8f;
    float nr = fmaxf(sqrtf(nr2), eps);
    float nf = fmaxf(sqrtf(nf2) * (1.f / HH), eps);
    float sim = (dot * (1.f / HH)) / (nr * nf);
    float hidden_c = fmaxf(0.f, (1.f - sim) * 0.5f);
    float token_c = 1.f - teq * (1.f / HH);
    const float invW = 1.f / (float)WW;
    float mrp = trp * invW, mrc = trg * invW;
    float dmass = t6 * invW;
    float dcoh = 0.6f * (tss * invW) + 0.25f * mrp + 0.15f * mrc;
    float pattern_c = 1.f - (0.6f * best + 0.2f * mrp + 0.2f * mrc);
    float contr = fminf(1.f, fmaxf(0.f, 0.2f * hidden_c + 0.2f * token_c + 0.6f * pattern_c));

    out[0 * NPAIR + p] = contr;
    out[1 * NPAIR + p] = shift;
    out[2 * NPAIR + p] = sim;
    out[3 * NPAIR + p] = hidden_c;
    out[4 * NPAIR + p] = token_c;
    out[5 * NPAIR + p] = pattern_c;
    out[6 * NPAIR + p] = dmass;
    out[7 * NPAIR + p] = dcoh;
  }
}

extern "C" void kernel_launch(void* const* d_in, const int* in_sizes, int n_in,
                              void* d_out, int out_size) {
  (void)in_sizes; (void)n_in; (void)out_size;
  const float* hidden = (const float*)d_in[0];
  const float* anchor = (const float*)d_in[1];
  const int*   ids    = (const int*)d_in[2];
  const int*   aendp  = (const int*)d_in[3];
  cm_stream<<<NPAIR * CH + NPAIR, 256>>>(hidden, anchor, ids, aendp, (float*)d_out);
}

// round 13
// speedup vs baseline: 1.3483x; 1.1698x over previous
#include <cuda_runtime.h>

// Problem constants (fixed by setup_inputs: B=8,T=4096,D=1024,A=32,S=16,TTL=64)
#define NB_B 8
#define NB_T 4096
#define NB_D 1024
#define NB_A 32
#define SP   16
#define HH   256           // H = max(ttl*4, span*4)
#define WW   (HH - SP + 1) // 241
#define NPAIR (NB_B * NB_A)
#define CH   4             // column chunks (CTAs) per pair
#define CG   64            // float4 groups per chunk (256 floats)
#define NG   (NB_D / 4)    // 256 float4 groups per row
#define SRS  260           // srow padded stride (16B-aligned rows, 4-way STS conflict max)

// scratch
__device__ float g_rshift[NPAIR * HH * CH];  // per-(pair,row) chunk partial norms^2
__device__ float g_dot[NPAIR * CH];
__device__ float g_nf2[NPAIR * CH];
__device__ float g_nr2[NPAIR * CH];
__device__ unsigned int g_cnt[NPAIR];        // zero-init; reset by finalizer

__constant__ signed char c_alias[64] = {
  -1,-1,-1,-1,-1,-1,-1,-1,-1,-1,-1,
  11,-1,11,-1,-1,11,
  -1,-1,-1,-1,
  21,21,21,
  -1,-1,-1,-1,-1,-1,-1,
  31,31,31,
  -1,-1,-1,-1,-1,-1,-1,
  41,41,41,41,
  -1,-1,-1,-1,-1,-1,
  51,51,51,
  -1,-1,-1,-1,-1,-1,-1,-1,-1,-1
};

// ---- 1024 streaming CTAs (column slices) + 256 token/finalizer CTAs ----
__global__ void __launch_bounds__(256, 4) cm_stream(
    const float* __restrict__ hidden,
    const float* __restrict__ anchor,
    const int*   __restrict__ ids,
    const int*   __restrict__ aend,
    float*       __restrict__ out)
{
  const int blk  = blockIdx.x;
  const int tid  = threadIdx.x;
  const int lane = tid & 31;
  const int wp   = tid >> 5;

  if (blk < NPAIR * CH) {
    // ================= streaming CTA =================
    const int p     = blk >> 2;
    const int chunk = blk & 3;
    const int b     = p / NB_A;
    const int ae    = aend[p];
    const int start = ae + 1;

    // srow: per-lane row-norm partials [lane][row], padded stride SRS.
    // scs (column-sum combine) overlapped onto the same storage.
    __shared__ float srow[32 * SRS];     // 33.3 KB
    float4* scs = reinterpret_cast<float4*>(srow);
    __shared__ float  sfin[3 * 8];

    const float4* __restrict__ hb =
        reinterpret_cast<const float4*>(hidden)
        + ((size_t)b * NB_T + start) * NG + chunk * CG;
    const float4* __restrict__ af =
        reinterpret_cast<const float4*>(anchor) + (size_t)p * NG + chunk * CG;

    const float4 a0 = af[lane];
    const float4 a1 = af[lane + 32];
    float4 cs0 = make_float4(0.f,0.f,0.f,0.f);
    float4 cs1 = make_float4(0.f,0.f,0.f,0.f);

    const int row0 = wp * 32;   // warp owns 32 rows
    float* __restrict__ myrow = srow + lane * SRS;

#pragma unroll 1
    for (int it = 0; it < 8; it++) {
      const int r = row0 + it * 4;
      const float4* __restrict__ rp = hb + (size_t)r * NG;
      // 8 independent LDG.128 front-batched -> MLP 8
      float4 x[4], y[4];
#pragma unroll
      for (int j = 0; j < 4; j++) {
        x[j] = rp[(size_t)j * NG + lane];
        y[j] = rp[(size_t)j * NG + lane + 32];
      }
      float v[4];
#pragma unroll
      for (int j = 0; j < 4; j++) {
        cs0.x += x[j].x; cs0.y += x[j].y; cs0.z += x[j].z; cs0.w += x[j].w;
        cs1.x += y[j].x; cs1.y += y[j].y; cs1.z += y[j].z; cs1.w += y[j].w;
        float dx = x[j].x - a0.x, dy = x[j].y - a0.y;
        float dz = x[j].z - a0.z, dw = x[j].w - a0.w;
        float s = dx*dx + dy*dy + dz*dz + dw*dw;
        dx = y[j].x - a1.x; dy = y[j].y - a1.y;
        dz = y[j].z - a1.z; dw = y[j].w - a1.w;
        v[j] = s + dx*dx + dy*dy + dz*dz + dw*dw;
      }
      // one STS.128: (lane*SRS + r)*4 bytes, SRS*4=1040 ≡ 0 (mod 16), r%4==0
      *reinterpret_cast<float4*>(myrow + r) = make_float4(v[0], v[1], v[2], v[3]);
    }
    __syncthreads();

    // row-sum transpose: thread t reduces row t's 32 lane-partials (conflict-free)
    float rowsum = 0.f;
#pragma unroll
    for (int l = 0; l < 32; l++) rowsum += srow[l * SRS + tid];
    g_rshift[((size_t)p * HH + tid) * CH + chunk] = rowsum;

    __syncthreads();   // srow reads complete before scs (aliased) is written

    // combine warps' column sums -> chunk scalars
    scs[wp * 64 + lane]      = cs0;
    scs[wp * 64 + lane + 32] = cs1;
    __syncthreads();

    if (tid < 64) {
      float4 t = scs[tid];
#pragma unroll
      for (int w = 1; w < 8; w++) {
        float4 u = scs[w * 64 + tid];
        t.x += u.x; t.y += u.y; t.z += u.z; t.w += u.w;
      }
      float4 a = af[tid];
      float dot = a.x*t.x + a.y*t.y + a.z*t.z + a.w*t.w;
      float nf2 = t.x*t.x + t.y*t.y + t.z*t.z + t.w*t.w;
      float nr2 = a.x*a.x + a.y*a.y + a.z*a.z + a.w*a.w;
#pragma unroll
      for (int o = 16; o; o >>= 1) {
        dot += __shfl_xor_sync(0xffffffffu, dot, o);
        nf2 += __shfl_xor_sync(0xffffffffu, nf2, o);
        nr2 += __shfl_xor_sync(0xffffffffu, nr2, o);
      }
      if (lane == 0) {
        sfin[wp * 3 + 0] = dot; sfin[wp * 3 + 1] = nf2; sfin[wp * 3 + 2] = nr2;
      }
    }
    __syncthreads();
    if (tid == 0) {
      g_dot[blk] = sfin[0] + sfin[3];
      g_nf2[blk] = sfin[1] + sfin[4];
      g_nr2[blk] = sfin[2] + sfin[5];
      // release-publish this chunk (no MEMBAR/IVALL; ordering at L2)
      asm volatile("red.release.gpu.global.add.u32 [%0], 1;"
                   :: "l"(&g_cnt[p]) : "memory");
    }
    return;
  }

  // ================= token + finalizer CTA (one per pair) =================
  const int p = blk - NPAIR * CH;
  const int b = p / NB_A;
  const int ae    = aend[p];
  const int start = ae + 1;

  __shared__ float sred[56];
  __shared__ int   ftok[HH];
  __shared__ int   sp_[SP];
  __shared__ signed char s_alias[64];
  __shared__ int   s_root, s_has, s_atok;
  __shared__ float s_invden;
  __shared__ unsigned long long s_spanmask, s_cmask;

  if (tid < 64) s_alias[tid] = c_alias[tid];
  ftok[tid] = ids[b * NB_T + start + tid];
  if (tid < SP) sp_[tid] = ids[b * NB_T + ae - (SP - 1) + tid];
  if (tid == 0) s_atok = ids[b * NB_T + ae];
  __syncthreads();

  if (tid == 0) {
    int root = -1;
    for (int s = 0; s < SP; s++) {
      int al = s_alias[sp_[s]];
      if (al >= 0) { root = al; break; }
    }
    if (root < 0) {
      int counts[SP]; int maxc = 0;
      for (int s = 0; s < SP; s++) {
        int c2 = 0;
        for (int s2 = 0; s2 < SP; s2++) c2 += (sp_[s2] == sp_[s]);
        counts[s] = c2; if (c2 > maxc) maxc = c2;
      }
      int mode = 64;
      for (int s = 0; s < SP; s++)
        if (counts[s] == maxc && sp_[s] < mode) mode = sp_[s];
      root = mode;
    }
    unsigned long long smask = 0ull; int den = 0;
    for (int s = 0; s < SP; s++) {
      bool first = true;
      for (int s2 = 0; s2 < s; s2++)
        if (sp_[s2] == sp_[s]) { first = false; break; }
      if (first) { den++; smask |= (1ull << sp_[s]); }
    }
    s_root = root;
    s_spanmask = smask;
    s_invden = 1.f / (float)den;
    s_has = (root == 11 || root == 21 || root == 31 || root == 41 || root == 51) ? 1 : 0;
    unsigned long long cm = 0ull;
    switch (root) {
      case 11: cm = (1ull<<11)|(1ull<<13)|(1ull<<16); break;
      case 21: cm = (1ull<<14)|(1ull<<15)|(1ull<<21)|(1ull<<22)|(1ull<<23); break;
      case 31: cm = (1ull<<15)|(1ull<<31)|(1ull<<32)|(1ull<<33); break;
      case 41: cm = (1ull<<41)|(1ull<<42)|(1ull<<43)|(1ull<<44); break;
      case 51: cm = (1ull<<15)|(1ull<<51)|(1ull<<52)|(1ull<<53); break;
      default: break;
    }
    s_cmask = cm;
  }
  __syncthreads();

  int myeq = (ftok[tid] == s_atok) ? 1 : 0;

  float sims = -1e30f, rootp = 0.f, regime = 0.f, ssum = 0.f;
  int c06 = 0;
  if (tid < WW) {
    const int root = s_root;
    const unsigned long long cmask = s_cmask;
    float exact = 0.f, positional = 0.f;
    unsigned long long wmask = 0ull;
    int c_rp = 0, c_al = 0, c_hd = 0;
#pragma unroll
    for (int s = 0; s < SP; s++) {
      int t = ftok[tid + s];
      wmask |= (1ull << t);
      if (t == sp_[s]) { exact += 1.f; positional += (1.0f - 0.04f * (float)s); }
      c_rp += (t == root);
      c_al += ((int)s_alias[t] == root);
      c_hd += (int)((cmask >> t) & 1ull);
    }
    exact *= (1.f / 16.f);
    positional *= (1.f / 11.2f);
    float overlap = (float)__popcll(wmask & s_spanmask) * s_invden;
    rootp = (float)c_rp * (1.f / 16.f);
    float aliasc = (float)c_al * (1.f / 16.f);
    float hard   = (float)c_hd * (1.f / 16.f);
    regime = s_has ? (0.55f * hard  + 0.2f * overlap + 0.15f * aliasc + 0.1f  * rootp)
                   : (0.45f * exact + 0.3f * overlap + 0.1f  * aliasc + 0.15f * rootp);
    float sv = 0.25f * exact + 0.15f * overlap + 0.35f * positional + 0.25f * regime;
    sims = sv; ssum = sv;
    c06 = (sv >= 0.6f) ? 1 : 0;
  }

  float msims = sims, srp = rootp, srg = regime, sss = ssum;
  int ceq = myeq, c6 = c06;
#pragma unroll
  for (int o = 16; o; o >>= 1) {
    msims = fmaxf(msims, __shfl_xor_sync(0xffffffffu, msims, o));
    srp += __shfl_xor_sync(0xffffffffu, srp, o);
    srg += __shfl_xor_sync(0xffffffffu, srg, o);
    sss += __shfl_xor_sync(0xffffffffu, sss, o);
    ceq += __shfl_xor_sync(0xffffffffu, ceq, o);
    c6  += __shfl_xor_sync(0xffffffffu, c6, o);
  }
  if (lane == 0) {
    sred[wp]      = msims;
    sred[8 + wp]  = srp;
    sred[16 + wp] = srg;
    sred[24 + wp] = sss;
    sred[32 + wp] = (float)ceq;
    sred[40 + wp] = (float)c6;
  }
  __syncthreads();

  // token scalars (held in tid0 registers across the wait)
  float best = -1e30f, trp = 0.f, trg = 0.f, tss = 0.f, teq = 0.f, t6 = 0.f;
  if (tid == 0) {
    for (int k = 0; k < 8; k++) {
      best = fmaxf(best, sred[k]);
      trp += sred[8 + k]; trg += sred[16 + k]; tss += sred[24 + k];
      teq += sred[32 + k]; t6 += sred[40 + k];
    }
    // acquire-spin until this pair's 4 streaming chunks have published
    unsigned int v;
    do {
      asm volatile("ld.acquire.gpu.global.u32 %0, [%1];"
                   : "=r"(v) : "l"(&g_cnt[p]) : "memory");
      if (v == CH) break;
      __nanosleep(64);
    } while (1);
    g_cnt[p] = 0;   // reset for next graph replay (kernel boundary orders it)
  }
  __syncthreads();

  // row-norm finalization: thread tid owns row tid
  float4 rp4 = reinterpret_cast<const float4*>(g_rshift)[p * HH + tid];
  float rn = sqrtf(rp4.x + rp4.y + rp4.z + rp4.w);
#pragma unroll
  for (int o = 16; o; o >>= 1) rn += __shfl_xor_sync(0xffffffffu, rn, o);
  if (lane == 0) sred[48 + wp] = rn;
  __syncthreads();

  if (tid == 0) {
    float sh = 0.f;
#pragma unroll
    for (int k = 0; k < 8; k++) sh += sred[48 + k];
    float shift = sh * (1.f / HH);

    float dot = 0.f, nf2 = 0.f, nr2 = 0.f;
#pragma unroll
    for (int c = 0; c < CH; c++) {
      dot += g_dot[p * CH + c];
      nf2 += g_nf2[p * CH + c];
      nr2 += g_nr2[p * CH + c];
    }
    const float eps = 1e-8f;
    float nr = fmaxf(sqrtf(nr2), eps);
    float nf = fmaxf(sqrtf(nf2) * (1.f / HH), eps);
    float sim = (dot * (1.f / HH)) / (nr * nf);
    float hidden_c = fmaxf(0.f, (1.f - sim) * 0.5f);
    float token_c = 1.f - teq * (1.f / HH);
    const float invW = 1.f / (float)WW;
    float mrp = trp * invW, mrc = trg * invW;
    float dmass = t6 * invW;
    float dcoh = 0.6f * (tss * invW) + 0.25f * mrp + 0.15f * mrc;
    float pattern_c = 1.f - (0.6f * best + 0.2f * mrp + 0.2f * mrc);
    float contr = fminf(1.f, fmaxf(0.f, 0.2f * hidden_c + 0.2f * token_c + 0.6f * pattern_c));

    out[0 * NPAIR + p] = contr;
    out[1 * NPAIR + p] = shift;
    out[2 * NPAIR + p] = sim;
    out[3 * NPAIR + p] = hidden_c;
    out[4 * NPAIR + p] = token_c;
    out[5 * NPAIR + p] = pattern_c;
    out[6 * NPAIR + p] = dmass;
    out[7 * NPAIR + p] = dcoh;
  }
}

extern "C" void kernel_launch(void* const* d_in, const int* in_sizes, int n_in,
                              void* d_out, int out_size) {
  (void)in_sizes; (void)n_in; (void)out_size;
  const float* hidden = (const float*)d_in[0];
  const float* anchor = (const float*)d_in[1];
  const int*   ids    = (const int*)d_in[2];
  const int*   aendp  = (const int*)d_in[3];
  cm_stream<<<NPAIR * CH + NPAIR, 256>>>(hidden, anchor, ids, aendp, (float*)d_out);
}